// round 15
// baseline (speedup 1.0000x reference)
#include <cuda_runtime.h>
#include <math.h>

// Problem constants
#define NBATCH   64
#define NCH      128
#define NPTS     256           // 16x16 image grid
#define MAPS     32            // BEV map size
#define NCELLS   (MAPS*MAPS)   // 1024
#define HMAXV    14
#define GROUPS   16            // channel groups per batch
#define CH_PER   (NCH / GROUPS)   // 8
#define NBMW     (NCELLS / 32)    // 32 bitmap words
#define MAXDUP   128

__device__ __forceinline__ void cp_async16(void* smem_dst, const void* gmem_src) {
    unsigned saddr = (unsigned)__cvta_generic_to_shared(smem_dst);
    asm volatile("cp.async.cg.shared.global [%0], [%1], 16;\n"
                 :: "r"(saddr), "l"(gmem_src) : "memory");
}
__device__ __forceinline__ void cp_async_commit() {
    asm volatile("cp.async.commit_group;\n" ::: "memory");
}
__device__ __forceinline__ void cp_async_wait_all() {
    asm volatile("cp.async.wait_group 0;\n" ::: "memory");
}

__global__ __launch_bounds__(256)
void voxelize_kernel(const float* __restrict__ features,   // (64,128,256)
                     const float* __restrict__ depth,      // (64,1,256)
                     const float* __restrict__ cam,        // (3,256)
                     float* __restrict__ out)              // (64,128,32,32)
{
    __shared__ __align__(16) int      win[NCELLS];          // packed (y<<8)|tid
    __shared__ __align__(16) float    sf [CH_PER * NPTS];   // staged features (8KB)
    __shared__ unsigned               sbm[NBMW];            // has-extra bitmap
    __shared__ int                    duplist[MAXDUP];      // packed (cell<<8)|tid
    __shared__ int                    dupcnt;

    const int tid = threadIdx.x;        // 0..255 == point id
    const int b   = blockIdx.y;         // batch
    const int g   = blockIdx.x;         // channel group
    const int cl4 = tid * 4;            // this thread's 4 cells

    // ---- 1. fire async staging FIRST (no register dependency — pure overlap) ----
    const float* __restrict__ fb = features + (size_t)(b * NCH + g * CH_PER) * NPTS;
    #pragma unroll
    for (int i = 0; i < (CH_PER * NPTS / 4) / 256; i++)     // 2 x 16B per thread
        cp_async16(&sf[(tid + i * 256) * 4], fb + (tid + i * 256) * 4);
    cp_async_commit();

    // ---- 2. depth/cam loads (L2-hot after first block) ----
    const float d  = depth[b * NPTS + tid];
    const float cx = cam[          tid];
    const float cy = cam[  NPTS  + tid];
    const float cz = cam[2*NPTS  + tid];

    // ---- 3. init winner table / bitmap (overlaps load latency) ----
    *reinterpret_cast<int4*>(&win[cl4]) = make_int4(-1, -1, -1, -1);
    if (tid < NBMW) sbm[tid] = 0u;
    if (tid == 0) dupcnt = 0;

    // ---- 4. per-point voxel index math (bit-exact vs JAX float32) ----
    const float px = __fmul_rn(d, cx);
    const float py = __fadd_rn(__fmul_rn(d, cy), 1.72f);   // + CAM_HEIGHT
    const float pz = __fmul_rn(d, cz);

    const float CELLF = 0.1f;  // float32(3.2/32)
    const int xi = (int)floorf(__fdiv_rn(px, CELLF)) + (MAPS / 2);
    const int yi = (int)floorf(__fdiv_rn(py, CELLF));
    const int zi = (int)floorf(__fdiv_rn(pz, CELLF)) + MAPS;

    const bool valid = (xi >= 0) & (xi < MAPS) & (zi >= 0) & (zi < MAPS) & (yi < HMAXV);

    // replicate reference flat index semantics: flat = (z*32+x)*14 + y
    int cell = -1, ye = -1;
    if (valid) {
        const int vflat = (zi * MAPS + xi) * HMAXV + yi;
        if (vflat >= 0) {
            cell = vflat / HMAXV;           // ye in [0,13]
            ye   = vflat - cell * HMAXV;
        }
    }
    __syncthreads();   // b1: init visible (cp.async still in flight)

    // ---- 5. packed winner max (y major, tid minor) ----
    if (cell >= 0) atomicMax(&win[cell], (ye << 8) | tid);
    __syncthreads();   // b2: winners final

    // ---- 6. losers tied at winning voxel -> duplist + bitmap bit (rare) ----
    if (cell >= 0) {
        const int w = win[cell];
        if ((w >> 8) == ye && (w & 255) != tid) {
            const int slot = atomicAdd(&dupcnt, 1);
            if (slot < MAXDUP) duplist[slot] = (cell << 8) | tid;
            atomicOr(&sbm[cell >> 5], 1u << (cell & 31));
        }
    }
    cp_async_wait_all();   // staged features complete (long since, ideally)
    __syncthreads();       // b3: dup data + staging visible

    // ---- 7. resolve this thread's 4 cells once (channel-invariant) ----
    const int4 w4 = *reinterpret_cast<const int4*>(&win[cl4]);
    const int f0 = (w4.x < 0) ? -1 : (w4.x & 255);
    const int f1 = (w4.y < 0) ? -1 : (w4.y & 255);
    const int f2 = (w4.z < 0) ? -1 : (w4.z & 255);
    const int f3 = (w4.w < 0) ? -1 : (w4.w & 255);
    const bool hasextra = (sbm[cl4 >> 5] >> (cl4 & 31)) & 0xF;   // O(1)

    float* __restrict__ ob = out + (size_t)(b * NCH + g * CH_PER) * NCELLS + cl4;

    if (!hasextra) {
        // common path: predicated smem gathers + coalesced STG.128
        #pragma unroll
        for (int c = 0; c < CH_PER; c++) {
            const float* __restrict__ frow = sf + c * NPTS;
            float4 v = make_float4(0.f, 0.f, 0.f, 0.f);
            if (f0 >= 0) v.x = frow[f0];
            if (f1 >= 0) v.y = frow[f1];
            if (f2 >= 0) v.z = frow[f2];
            if (f3 >= 0) v.w = frow[f3];
            *reinterpret_cast<float4*>(ob + c * NCELLS) = v;
        }
    } else {
        // rare threads owning a multi-contributor cell
        const int ne = min(dupcnt, MAXDUP);
        #pragma unroll 4
        for (int c = 0; c < CH_PER; c++) {
            const float* __restrict__ frow = sf + c * NPTS;
            float4 v = make_float4(0.f, 0.f, 0.f, 0.f);
            if (f0 >= 0) v.x = frow[f0];
            if (f1 >= 0) v.y = frow[f1];
            if (f2 >= 0) v.z = frow[f2];
            if (f3 >= 0) v.w = frow[f3];
            for (int k = 0; k < ne; k++) {
                const int e  = duplist[k];
                const int dc = e >> 8;
                const int dt = e & 255;
                if      (dc == cl4    ) v.x += frow[dt];
                else if (dc == cl4 + 1) v.y += frow[dt];
                else if (dc == cl4 + 2) v.z += frow[dt];
                else if (dc == cl4 + 3) v.w += frow[dt];
            }
            *reinterpret_cast<float4*>(ob + c * NCELLS) = v;
        }
    }
}

extern "C" void kernel_launch(void* const* d_in, const int* in_sizes, int n_in,
                              void* d_out, int out_size)
{
    const float* features = (const float*)d_in[0];   // 64*128*16*16
    const float* depth    = (const float*)d_in[1];   // 64*1*16*16
    const float* cam      = (const float*)d_in[2];   // 3*256
    float*       out      = (float*)d_out;           // 64*128*32*32

    dim3 grid(GROUPS, NBATCH);
    voxelize_kernel<<<grid, 256>>>(features, depth, cam, out);
}

// round 16
// speedup vs baseline: 1.6704x; 1.6704x over previous
#include <cuda_runtime.h>
#include <math.h>

// Problem constants
#define NBATCH   64
#define NCH      128
#define NPTS     256           // 16x16 image grid
#define MAPS     32            // BEV map size
#define NCELLS   (MAPS*MAPS)   // 1024
#define HMAXV    14
#define GROUPS   32            // channel groups per batch (2048 blocks)
#define CH_PER   (NCH / GROUPS)   // 4
#define NBMW     (NCELLS / 32)    // 32 bitmap words
#define MAXDUP   128

__global__ __launch_bounds__(256)
void voxelize_kernel(const float* __restrict__ features,   // (64,128,256)
                     const float* __restrict__ depth,      // (64,1,256)
                     const float* __restrict__ cam,        // (3,256)
                     float* __restrict__ out)              // (64,128,32,32)
{
    __shared__ __align__(16) int      win[NCELLS];          // packed (y<<8)|tid
    __shared__ __align__(16) float    sf [CH_PER * NPTS];   // staged features (4KB)
    __shared__ unsigned               sbm[NBMW];            // has-extra bitmap
    __shared__ int                    duplist[MAXDUP];      // packed (cell<<8)|tid
    __shared__ int                    dupcnt;

    const int tid = threadIdx.x;        // 0..255 == point id
    const int b   = blockIdx.y;         // batch
    const int g   = blockIdx.x;         // channel group
    const int cl4 = tid * 4;            // this thread's 4 cells

    // ---- front-batch ALL global loads (independent; max overlap) ----
    const float d  = depth[b * NPTS + tid];
    const float cx = cam[          tid];
    const float cy = cam[  NPTS  + tid];
    const float cz = cam[2*NPTS  + tid];

    // staging: exactly 1 float4 per thread (coalesced LDG.128)
    const float* __restrict__ fb = features + (size_t)(b * NCH + g * CH_PER) * NPTS;
    const float4 stage = reinterpret_cast<const float4*>(fb)[tid];

    // ---- init winner table / bitmap (overlaps load latency) ----
    *reinterpret_cast<int4*>(&win[cl4]) = make_int4(-1, -1, -1, -1);
    if (tid < NBMW) sbm[tid] = 0u;
    if (tid == 0) dupcnt = 0;

    // ---- per-point voxel index math (bit-exact vs JAX float32) ----
    const float px = __fmul_rn(d, cx);
    const float py = __fadd_rn(__fmul_rn(d, cy), 1.72f);   // + CAM_HEIGHT
    const float pz = __fmul_rn(d, cz);

    const float CELLF = 0.1f;  // float32(3.2/32)
    const int xi = (int)floorf(__fdiv_rn(px, CELLF)) + (MAPS / 2);
    const int yi = (int)floorf(__fdiv_rn(py, CELLF));
    const int zi = (int)floorf(__fdiv_rn(pz, CELLF)) + MAPS;

    const bool valid = (xi >= 0) & (xi < MAPS) & (zi >= 0) & (zi < MAPS) & (yi < HMAXV);

    // replicate reference flat index semantics: flat = (z*32+x)*14 + y
    int cell = -1, ye = -1;
    if (valid) {
        const int vflat = (zi * MAPS + xi) * HMAXV + yi;
        if (vflat >= 0) {
            cell = vflat / HMAXV;           // ye in [0,13]
            ye   = vflat - cell * HMAXV;
        }
    }

    // park staged data in smem (STS retires when LDG returns)
    reinterpret_cast<float4*>(sf)[tid] = stage;
    __syncthreads();   // b1: init + staging visible

    // ---- phase 1: packed winner max (y major, tid minor) ----
    if (cell >= 0) atomicMax(&win[cell], (ye << 8) | tid);
    __syncthreads();   // b2: winners final

    // ---- phase 2: losers tied at winning voxel -> duplist + bitmap (rare) ----
    if (cell >= 0) {
        const int w = win[cell];
        if ((w >> 8) == ye && (w & 255) != tid) {
            const int slot = atomicAdd(&dupcnt, 1);
            if (slot < MAXDUP) duplist[slot] = (cell << 8) | tid;
            atomicOr(&sbm[cell >> 5], 1u << (cell & 31));
        }
    }
    __syncthreads();   // b3: dup data visible

    // ---- resolve this thread's 4 cells once (channel-invariant) ----
    const int4 w4 = *reinterpret_cast<const int4*>(&win[cl4]);
    const int f0 = (w4.x < 0) ? -1 : (w4.x & 255);
    const int f1 = (w4.y < 0) ? -1 : (w4.y & 255);
    const int f2 = (w4.z < 0) ? -1 : (w4.z & 255);
    const int f3 = (w4.w < 0) ? -1 : (w4.w & 255);
    const bool hasextra = (sbm[cl4 >> 5] >> (cl4 & 31)) & 0xF;   // O(1)

    float* __restrict__ ob = out + (size_t)(b * NCH + g * CH_PER) * NCELLS + cl4;

    if (!hasextra) {
        // common path: predicated smem gathers + coalesced STG.128
        #pragma unroll
        for (int c = 0; c < CH_PER; c++) {
            const float* __restrict__ frow = sf + c * NPTS;
            float4 v = make_float4(0.f, 0.f, 0.f, 0.f);
            if (f0 >= 0) v.x = frow[f0];
            if (f1 >= 0) v.y = frow[f1];
            if (f2 >= 0) v.z = frow[f2];
            if (f3 >= 0) v.w = frow[f3];
            *reinterpret_cast<float4*>(ob + c * NCELLS) = v;
        }
    } else {
        // rare threads owning a multi-contributor cell
        const int ne = min(dupcnt, MAXDUP);
        #pragma unroll
        for (int c = 0; c < CH_PER; c++) {
            const float* __restrict__ frow = sf + c * NPTS;
            float4 v = make_float4(0.f, 0.f, 0.f, 0.f);
            if (f0 >= 0) v.x = frow[f0];
            if (f1 >= 0) v.y = frow[f1];
            if (f2 >= 0) v.z = frow[f2];
            if (f3 >= 0) v.w = frow[f3];
            for (int k = 0; k < ne; k++) {
                const int e  = duplist[k];
                const int dc = e >> 8;
                const int dt = e & 255;
                if      (dc == cl4    ) v.x += frow[dt];
                else if (dc == cl4 + 1) v.y += frow[dt];
                else if (dc == cl4 + 2) v.z += frow[dt];
                else if (dc == cl4 + 3) v.w += frow[dt];
            }
            *reinterpret_cast<float4*>(ob + c * NCELLS) = v;
        }
    }
}

extern "C" void kernel_launch(void* const* d_in, const int* in_sizes, int n_in,
                              void* d_out, int out_size)
{
    const float* features = (const float*)d_in[0];   // 64*128*16*16
    const float* depth    = (const float*)d_in[1];   // 64*1*16*16
    const float* cam      = (const float*)d_in[2];   // 3*256
    float*       out      = (float*)d_out;           // 64*128*32*32

    dim3 grid(GROUPS, NBATCH);
    voxelize_kernel<<<grid, 256>>>(features, depth, cam, out);
}

// round 17
// speedup vs baseline: 1.7649x; 1.0565x over previous
#include <cuda_runtime.h>
#include <math.h>

// Problem constants
#define NBATCH   64
#define NCH      128
#define NPTS     256           // 16x16 image grid
#define MAPS     32            // BEV map size
#define NCELLS   (MAPS*MAPS)   // 1024
#define HMAXV    14
#define GROUPS   32            // channel groups per batch
#define CH_PER   (NCH / GROUPS)   // 4
#define GPAIR    2             // groups served per block
#define NTHREADS 512

__global__ __launch_bounds__(NTHREADS)
void voxelize_kernel(const float* __restrict__ features,   // (64,128,256)
                     const float* __restrict__ depth,      // (64,1,256)
                     const float* __restrict__ cam,        // (3,256)
                     float* __restrict__ out)              // (64,128,32,32)
{
    __shared__ __align__(16) int   win[NCELLS];              // packed (y<<8)|tid
    __shared__ __align__(16) float sf[GPAIR][CH_PER * NPTS]; // 2 x 4KB staged slices

    const int tid  = threadIdx.x;        // 0..511
    const int pid  = tid & 255;          // point id / cell-quad id
    const int half = tid >> 8;           // which group of the pair
    const int b    = blockIdx.y;         // batch
    const int g2   = blockIdx.x;         // group pair
    const int cl4  = pid * 4;            // this thread's 4 cells

    // ---- front-batch global loads ----
    float d = 0.f, cx = 0.f, cy = 0.f, cz = 0.f;
    if (half == 0) {
        d  = depth[b * NPTS + pid];
        cx = cam[          pid];
        cy = cam[  NPTS  + pid];
        cz = cam[2*NPTS  + pid];
    }
    // each half stages its group's slice: 1 float4 per thread (coalesced LDG.128)
    const int gg = g2 * GPAIR + half;
    const float* __restrict__ fb = features + (size_t)(b * NCH + gg * CH_PER) * NPTS;
    const float4 stage = reinterpret_cast<const float4*>(fb)[pid];

    // ---- init winner table (half 0 threads own 4 cells each) ----
    if (half == 0)
        *reinterpret_cast<int4*>(&win[cl4]) = make_int4(-1, -1, -1, -1);

    // ---- per-point voxel index math (bit-exact vs JAX float32), half 0 only ----
    int cell = -1, ye = -1;
    if (half == 0) {
        const float px = __fmul_rn(d, cx);
        const float py = __fadd_rn(__fmul_rn(d, cy), 1.72f);   // + CAM_HEIGHT
        const float pz = __fmul_rn(d, cz);

        const float CELLF = 0.1f;  // float32(3.2/32)
        const int xi = (int)floorf(__fdiv_rn(px, CELLF)) + (MAPS / 2);
        const int yi = (int)floorf(__fdiv_rn(py, CELLF));
        const int zi = (int)floorf(__fdiv_rn(pz, CELLF)) + MAPS;

        const bool valid = (xi >= 0) & (xi < MAPS) & (zi >= 0) & (zi < MAPS) & (yi < HMAXV);

        // replicate reference flat index semantics: flat = (z*32+x)*14 + y
        if (valid) {
            const int vflat = (zi * MAPS + xi) * HMAXV + yi;
            if (vflat >= 0) {
                cell = vflat / HMAXV;           // ye in [0,13]
                ye   = vflat - cell * HMAXV;
            }
        }
    }

    // park staged slice in smem
    reinterpret_cast<float4*>(sf[half])[pid] = stage;
    __syncthreads();   // b1: init + staging visible

    // ---- phase 1: packed winner max (y major, tid minor) ----
    if (cell >= 0) atomicMax(&win[cell], (ye << 8) | pid);
    __syncthreads();   // b2: winners final

    // ---- phase 2: losers tied at winning voxel fold their staged rows into
    //      the winner's rows (both groups). Rare (~2 points/block). ----
    if (cell >= 0) {
        const int w = win[cell];
        if ((w >> 8) == ye) {
            const int wt = w & 255;
            if (wt != pid) {
                #pragma unroll
                for (int h = 0; h < GPAIR; h++)
                    #pragma unroll
                    for (int c = 0; c < CH_PER; c++)
                        atomicAdd(&sf[h][c * NPTS + wt], sf[h][c * NPTS + pid]);
            }
        }
    }
    __syncthreads();   // b3: fixups visible

    // ---- epilogue: branch-free predicated gathers + coalesced STG.128 ----
    const int4 w4 = *reinterpret_cast<const int4*>(&win[cl4]);
    const int f0 = (w4.x < 0) ? -1 : (w4.x & 255);
    const int f1 = (w4.y < 0) ? -1 : (w4.y & 255);
    const int f2 = (w4.z < 0) ? -1 : (w4.z & 255);
    const int f3 = (w4.w < 0) ? -1 : (w4.w & 255);

    const float* __restrict__ sfh = sf[half];
    float* __restrict__ ob = out + (size_t)(b * NCH + gg * CH_PER) * NCELLS + cl4;

    #pragma unroll
    for (int c = 0; c < CH_PER; c++) {
        const float* __restrict__ frow = sfh + c * NPTS;
        float4 v = make_float4(0.f, 0.f, 0.f, 0.f);
        if (f0 >= 0) v.x = frow[f0];
        if (f1 >= 0) v.y = frow[f1];
        if (f2 >= 0) v.z = frow[f2];
        if (f3 >= 0) v.w = frow[f3];
        *reinterpret_cast<float4*>(ob + c * NCELLS) = v;
    }
}

extern "C" void kernel_launch(void* const* d_in, const int* in_sizes, int n_in,
                              void* d_out, int out_size)
{
    const float* features = (const float*)d_in[0];   // 64*128*16*16
    const float* depth    = (const float*)d_in[1];   // 64*1*16*16
    const float* cam      = (const float*)d_in[2];   // 3*256
    float*       out      = (float*)d_out;           // 64*128*32*32

    dim3 grid(GROUPS / GPAIR, NBATCH);               // (16, 64) = 1024 blocks
    voxelize_kernel<<<grid, NTHREADS>>>(features, depth, cam, out);
}